// round 1
// baseline (speedup 1.0000x reference)
#include <cuda_runtime.h>
#include <cstdint>
#include <cstddef>

// ---------------------------------------------------------------------------
// MinGRU (2 layers): GEMM0 -> scan0 -> GEMM1 -> scan1
// B=8, S=4096, D=H=1024, E=2H=2048, M=B*S=32768, K=1024 for both layers.
// GEMM: tf32 mma.sync.m16n8k8, 128x128x16 tiles, cp.async double buffer.
// GEMM output layout: channel-major (B, 2H, S) so scans read contiguously.
// Scan: 1 warp / channel, lane = 128 contiguous steps, warp shfl scan of
//       affine maps (C,V): h' = C*h + V (linear space; all-positive).
// ---------------------------------------------------------------------------

#define B_ 8
#define S_ 4096
#define K_ 1024
#define H_ 1024
#define E_ 2048
#define M_ (B_ * S_)

// scratch (no cudaMalloc allowed)
__device__ float g_gbuf[(size_t)B_ * E_ * S_];    // 268 MB: GEMM out (B,2H,S)
__device__ float g_h1buf[(size_t)B_ * H_ * S_];   // 134 MB: layer-0 h (B,H,S)

// ------------------------------- GEMM --------------------------------------

#define BM 128
#define BN 128
#define BK 16
#define SASTR 20      // token-major smem A: [m][k], stride 20 (conflict-free frags)
#define SATSTR 136    // ch-major   smem A: [k][m], stride 136
#define SWSTR 20      // smem W: [e][k], stride 20
#define NT (K_ / BK)  // 64 k-tiles

__device__ __forceinline__ uint32_t f2tf(float x) {
    uint32_t y;
    asm volatile("cvt.rna.tf32.f32 %0, %1;" : "=r"(y) : "f"(x));
    return y;
}

__device__ __forceinline__ void cpasync16(uint32_t dst, const void* src) {
    asm volatile("cp.async.cg.shared.global [%0], [%1], 16;\n" ::"r"(dst), "l"(src));
}
__device__ __forceinline__ void cpcommit() { asm volatile("cp.async.commit_group;\n"); }
__device__ __forceinline__ void cpwait1() { asm volatile("cp.async.wait_group 1;\n"); }
__device__ __forceinline__ void cpwait0() { asm volatile("cp.async.wait_group 0;\n"); }

__device__ __forceinline__ void mma_tf32(float* c, const uint32_t* a, const uint32_t* b) {
    asm volatile(
        "mma.sync.aligned.m16n8k8.row.col.f32.tf32.tf32.f32 "
        "{%0,%1,%2,%3}, {%4,%5,%6,%7}, {%8,%9}, {%0,%1,%2,%3};\n"
        : "+f"(c[0]), "+f"(c[1]), "+f"(c[2]), "+f"(c[3])
        : "r"(a[0]), "r"(a[1]), "r"(a[2]), "r"(a[3]), "r"(b[0]), "r"(b[1]));
}

// ACH=false: A is token-major (M,K) row-major (layer 0 input x)
// ACH=true : A is channel-major (B,K,S): A[(b,s)][k] = A[b*K*S + k*S + s]
template <bool ACH>
__global__ __launch_bounds__(256, 2) void gemm_kernel(
    const float* __restrict__ A, const float* __restrict__ W,
    const float* __restrict__ bias, float* __restrict__ Cout)
{
    __shared__ float sA[2][BM * SASTR];  // token: 128*20=2560; ch uses 16*136=2176
    __shared__ float sW[2][BN * SWSTR];

    const int tid = threadIdx.x;
    const int warp = tid >> 5, lane = tid & 31;
    const int g = lane >> 2, q = lane & 3;
    const int mw = (warp & 1) * 64;
    const int nw = (warp >> 1) * 32;

    const int m0 = blockIdx.y * BM;
    const int b = m0 / S_;
    const int s0 = m0 % S_;
    const int e0 = blockIdx.x * BN;

    const float* Ablk;
    if (ACH) Ablk = A + (size_t)b * K_ * S_ + s0;  // + k*S_ + m_local
    else     Ablk = A + (size_t)m0 * K_;           // + m_local*K_ + k
    const float* Wblk = W + (size_t)e0 * K_;

    uint32_t saAddr[2], swAddr[2];
    saAddr[0] = (uint32_t)__cvta_generic_to_shared(&sA[0][0]);
    saAddr[1] = (uint32_t)__cvta_generic_to_shared(&sA[1][0]);
    swAddr[0] = (uint32_t)__cvta_generic_to_shared(&sW[0][0]);
    swAddr[1] = (uint32_t)__cvta_generic_to_shared(&sW[1][0]);

    auto loadTile = [&](int kt, int st) {
#pragma unroll
        for (int it = 0; it < 2; ++it) {
            int l = tid + it * 256;
            if (ACH) {
                int r = l >> 5;            // k row (0..15)
                int c = (l & 31) * 4;      // m col
                cpasync16(saAddr[st] + (uint32_t)(r * SATSTR + c) * 4,
                          Ablk + (size_t)(kt * BK + r) * S_ + c);
            } else {
                int r = l >> 2;            // m row (0..127)
                int c = (l & 3) * 4;       // k col
                cpasync16(saAddr[st] + (uint32_t)(r * SASTR + c) * 4,
                          Ablk + (size_t)r * K_ + kt * BK + c);
            }
        }
#pragma unroll
        for (int it = 0; it < 2; ++it) {
            int l = tid + it * 256;
            int r = l >> 2;
            int c = (l & 3) * 4;
            cpasync16(swAddr[st] + (uint32_t)(r * SWSTR + c) * 4,
                      Wblk + (size_t)r * K_ + kt * BK + c);
        }
    };

    float acc[4][4][4];
#pragma unroll
    for (int i = 0; i < 4; i++)
#pragma unroll
        for (int j = 0; j < 4; j++)
#pragma unroll
            for (int r = 0; r < 4; r++) acc[i][j][r] = 0.f;

    loadTile(0, 0);
    cpcommit();

    for (int t = 0; t < NT; ++t) {
        const int cur = t & 1;
        if (t + 1 < NT) {
            loadTile(t + 1, cur ^ 1);
            cpcommit();
            cpwait1();
        } else {
            cpwait0();
        }
        __syncthreads();

        const float* cA = sA[cur];
        const float* cW = sW[cur];
#pragma unroll
        for (int ks = 0; ks < 2; ++ks) {
            uint32_t af[4][4], bf[4][2];
            const int kc = ks * 8 + q;
#pragma unroll
            for (int i = 0; i < 4; i++) {
                const int mr = mw + i * 16 + g;
                if (ACH) {
                    af[i][0] = f2tf(cA[kc * SATSTR + mr]);
                    af[i][1] = f2tf(cA[kc * SATSTR + mr + 8]);
                    af[i][2] = f2tf(cA[(kc + 4) * SATSTR + mr]);
                    af[i][3] = f2tf(cA[(kc + 4) * SATSTR + mr + 8]);
                } else {
                    af[i][0] = f2tf(cA[mr * SASTR + kc]);
                    af[i][1] = f2tf(cA[(mr + 8) * SASTR + kc]);
                    af[i][2] = f2tf(cA[mr * SASTR + kc + 4]);
                    af[i][3] = f2tf(cA[(mr + 8) * SASTR + kc + 4]);
                }
            }
#pragma unroll
            for (int j = 0; j < 4; j++) {
                const int e = nw + j * 8 + g;
                bf[j][0] = f2tf(cW[e * SWSTR + kc]);
                bf[j][1] = f2tf(cW[e * SWSTR + kc + 4]);
            }
#pragma unroll
            for (int i = 0; i < 4; i++)
#pragma unroll
                for (int j = 0; j < 4; j++) mma_tf32(acc[i][j], af[i], bf[j]);
        }
        __syncthreads();
    }

    // epilogue: C[e][m] channel-major: Cout[b*E*S + e*S + s]
    float* Cblk = Cout + (size_t)b * E_ * S_ + (size_t)e0 * S_ + s0;
#pragma unroll
    for (int i = 0; i < 4; i++) {
        const int mr = mw + i * 16 + g;
#pragma unroll
        for (int j = 0; j < 4; j++) {
            const int e = nw + j * 8 + q * 2;
            const float bv0 = __ldg(bias + e0 + e);
            const float bv1 = __ldg(bias + e0 + e + 1);
            Cblk[(size_t)e * S_ + mr] = acc[i][j][0] + bv0;
            Cblk[(size_t)(e + 1) * S_ + mr] = acc[i][j][1] + bv1;
            Cblk[(size_t)e * S_ + mr + 8] = acc[i][j][2] + bv0;
            Cblk[(size_t)(e + 1) * S_ + mr + 8] = acc[i][j][3] + bv1;
        }
    }
}

// ------------------------------- Scan --------------------------------------

__device__ __forceinline__ float sigm(float x) { return 1.0f / (1.0f + __expf(-x)); }

__device__ __forceinline__ void step_cv(float gg, float hh, float& c, float& v) {
    const float z = sigm(gg);
    c = 1.0f - z;
    const float gl = (hh >= 0.f) ? (hh + 0.5f) : sigm(hh);
    v = z * gl;
}

// gh: (B, 2H, S) channel-major. TOKOUT=false -> out (B,H,S); true -> out (B,S,H)
template <bool TOKOUT>
__global__ __launch_bounds__(256) void scan_kernel(
    const float* __restrict__ gh, float* __restrict__ out)
{
    const int gwarp = (blockIdx.x * blockDim.x + threadIdx.x) >> 5;
    const int lane = threadIdx.x & 31;
    const int b = gwarp / H_;
    const int h = gwarp % H_;

    const float* gate = gh + (size_t)b * E_ * S_ + (size_t)h * S_;
    const float* hid = gate + (size_t)H_ * S_;
    const int sbase = lane * (S_ / 32);  // 128 per lane

    const float4* g4 = (const float4*)(gate + sbase);
    const float4* h4 = (const float4*)(hid + sbase);

    // pass 1: local affine composition over this lane's 128 steps
    float C = 1.f, V = 0.f;
#pragma unroll 4
    for (int i = 0; i < 32; i++) {
        const float4 gv = g4[i];
        const float4 hv = h4[i];
        const float* gp = (const float*)&gv;
        const float* hp = (const float*)&hv;
#pragma unroll
        for (int j = 0; j < 4; j++) {
            float c, v;
            step_cv(gp[j], hp[j], c, v);
            V = __fmaf_rn(c, V, v);
            C *= c;
        }
    }

    // warp inclusive scan of affine maps, then exclusive prefix
#pragma unroll
    for (int d = 1; d < 32; d <<= 1) {
        const float Cu = __shfl_up_sync(0xffffffffu, C, d);
        const float Vu = __shfl_up_sync(0xffffffffu, V, d);
        if (lane >= d) {
            V = __fmaf_rn(C, Vu, V);
            C *= Cu;
        }
    }
    const float Ce = __shfl_up_sync(0xffffffffu, C, 1);
    const float Ve = __shfl_up_sync(0xffffffffu, V, 1);
    float hcur = (lane == 0) ? 0.5f : __fmaf_rn(Ce, 0.5f, Ve);

    // pass 2: apply
    if (TOKOUT) {
        float* op = out + ((size_t)b * S_ + sbase) * H_ + h;
#pragma unroll 4
        for (int i = 0; i < 32; i++) {
            const float4 gv = g4[i];
            const float4 hv = h4[i];
            const float* gp = (const float*)&gv;
            const float* hp = (const float*)&hv;
#pragma unroll
            for (int j = 0; j < 4; j++) {
                float c, v;
                step_cv(gp[j], hp[j], c, v);
                hcur = __fmaf_rn(c, hcur, v);
                op[(size_t)(i * 4 + j) * H_] = hcur;
            }
        }
    } else {
        float4* op = (float4*)(out + (size_t)b * H_ * S_ + (size_t)h * S_ + sbase);
#pragma unroll 4
        for (int i = 0; i < 32; i++) {
            const float4 gv = g4[i];
            const float4 hv = h4[i];
            const float* gp = (const float*)&gv;
            const float* hp = (const float*)&hv;
            float4 res;
            float* rp = (float*)&res;
#pragma unroll
            for (int j = 0; j < 4; j++) {
                float c, v;
                step_cv(gp[j], hp[j], c, v);
                hcur = __fmaf_rn(c, hcur, v);
                rp[j] = hcur;
            }
            op[i] = res;
        }
    }
}

// ------------------------------ Launch -------------------------------------

extern "C" void kernel_launch(void* const* d_in, const int* in_sizes, int n_in,
                              void* d_out, int out_size)
{
    (void)in_sizes; (void)n_in; (void)out_size;
    const float* x = (const float*)d_in[0];
    const float* W0 = (const float*)d_in[1];
    const float* b0 = (const float*)d_in[2];
    const float* W1 = (const float*)d_in[3];
    const float* b1 = (const float*)d_in[4];
    float* out = (float*)d_out;

    float* gbuf = nullptr;
    float* h1 = nullptr;
    cudaGetSymbolAddress((void**)&gbuf, g_gbuf);
    cudaGetSymbolAddress((void**)&h1, g_h1buf);

    const dim3 gThr(256);
    const dim3 gGrid(E_ / BN, M_ / BM);  // (16, 256)
    const int scanBlocks = (B_ * H_) / 8;  // 8 warps/block -> 1024 blocks

    gemm_kernel<false><<<gGrid, gThr>>>(x, W0, b0, gbuf);
    scan_kernel<false><<<scanBlocks, 256>>>(gbuf, h1);
    gemm_kernel<true><<<gGrid, gThr>>>(h1, W1, b1, gbuf);
    scan_kernel<true><<<scanBlocks, 256>>>(gbuf, out);
}

// round 5
// speedup vs baseline: 1.2650x; 1.2650x over previous
#include <cuda_runtime.h>
#include <cstdint>
#include <cstddef>

// ---------------------------------------------------------------------------
// MinGRU (2 layers): GEMM0 -> scan0 -> GEMM1 -> scan1
// B=8, S=4096, D=H=1024, E=2H=2048, M=B*S=32768, K=1024.
// GEMM: tf32 mma.sync.m16n8k8, 128x128x16 tiles, cp.async double buffer
//       (legacy HMMA path: harness ptxas targets sm_103, no tcgen05).
// GEMM out: channel-major (B,2H,S) so scans read contiguously.
// Scan: warp/channel, single read pass (16 steps/lane in regs, 8 carried
//       iterations), smem-transposed coalesced writes for the (B,S,H) output.
// ---------------------------------------------------------------------------

#define B_ 8
#define S_ 4096
#define K_ 1024
#define H_ 1024
#define E_ 2048
#define M_ (B_ * S_)

// scratch (no cudaMalloc allowed)
__device__ float g_gbuf[(size_t)B_ * E_ * S_];    // 268 MB: GEMM out (B,2H,S)
__device__ float g_h1buf[(size_t)B_ * H_ * S_];   // 134 MB: layer-0 h (B,H,S)

// ------------------------------- GEMM --------------------------------------

#define BM 128
#define BN 128
#define BK 16
#define SASTR 20      // token-major smem A: [m][k], stride 20
#define SATSTR 136    // ch-major   smem A: [k][m], stride 136
#define SWSTR 20      // smem W: [e][k], stride 20
#define NT (K_ / BK)  // 64 k-tiles

__device__ __forceinline__ uint32_t f2tf(float x) {
    uint32_t y;
    asm volatile("cvt.rna.tf32.f32 %0, %1;" : "=r"(y) : "f"(x));
    return y;
}

__device__ __forceinline__ void cpasync16(uint32_t dst, const void* src) {
    asm volatile("cp.async.cg.shared.global [%0], [%1], 16;\n" ::"r"(dst), "l"(src));
}
__device__ __forceinline__ void cpcommit() { asm volatile("cp.async.commit_group;\n"); }
__device__ __forceinline__ void cpwait1() { asm volatile("cp.async.wait_group 1;\n"); }
__device__ __forceinline__ void cpwait0() { asm volatile("cp.async.wait_group 0;\n"); }

__device__ __forceinline__ void mma_tf32(float* c, const uint32_t* a, const uint32_t* b) {
    asm volatile(
        "mma.sync.aligned.m16n8k8.row.col.f32.tf32.tf32.f32 "
        "{%0,%1,%2,%3}, {%4,%5,%6,%7}, {%8,%9}, {%0,%1,%2,%3};\n"
        : "+f"(c[0]), "+f"(c[1]), "+f"(c[2]), "+f"(c[3])
        : "r"(a[0]), "r"(a[1]), "r"(a[2]), "r"(a[3]), "r"(b[0]), "r"(b[1]));
}

// ACH=false: A is token-major (M,K) row-major (layer 0 input x)
// ACH=true : A is channel-major (B,K,S): A[(b,s)][k] = A[b*K*S + k*S + s]
template <bool ACH>
__global__ __launch_bounds__(256, 2) void gemm_kernel(
    const float* __restrict__ A, const float* __restrict__ W,
    const float* __restrict__ bias, float* __restrict__ Cout)
{
    __shared__ float sA[2][BM * SASTR];
    __shared__ float sW[2][BN * SWSTR];

    const int tid = threadIdx.x;
    const int warp = tid >> 5, lane = tid & 31;
    const int g = lane >> 2, q = lane & 3;
    const int mw = (warp & 1) * 64;
    const int nw = (warp >> 1) * 32;

    const int m0 = blockIdx.y * BM;
    const int b = m0 / S_;
    const int s0 = m0 % S_;
    const int e0 = blockIdx.x * BN;

    const float* Ablk;
    if (ACH) Ablk = A + (size_t)b * K_ * S_ + s0;  // + k*S_ + m_local
    else     Ablk = A + (size_t)m0 * K_;           // + m_local*K_ + k
    const float* Wblk = W + (size_t)e0 * K_;

    uint32_t saAddr[2], swAddr[2];
    saAddr[0] = (uint32_t)__cvta_generic_to_shared(&sA[0][0]);
    saAddr[1] = (uint32_t)__cvta_generic_to_shared(&sA[1][0]);
    swAddr[0] = (uint32_t)__cvta_generic_to_shared(&sW[0][0]);
    swAddr[1] = (uint32_t)__cvta_generic_to_shared(&sW[1][0]);

    auto loadTile = [&](int kt, int st) {
#pragma unroll
        for (int it = 0; it < 2; ++it) {
            int l = tid + it * 256;
            if (ACH) {
                int r = l >> 5;            // k row (0..15)
                int c = (l & 31) * 4;      // m col
                cpasync16(saAddr[st] + (uint32_t)(r * SATSTR + c) * 4,
                          Ablk + (size_t)(kt * BK + r) * S_ + c);
            } else {
                int r = l >> 2;            // m row (0..127)
                int c = (l & 3) * 4;       // k col
                cpasync16(saAddr[st] + (uint32_t)(r * SASTR + c) * 4,
                          Ablk + (size_t)r * K_ + kt * BK + c);
            }
        }
#pragma unroll
        for (int it = 0; it < 2; ++it) {
            int l = tid + it * 256;
            int r = l >> 2;
            int c = (l & 3) * 4;
            cpasync16(swAddr[st] + (uint32_t)(r * SWSTR + c) * 4,
                      Wblk + (size_t)r * K_ + kt * BK + c);
        }
    };

    float acc[4][4][4];
#pragma unroll
    for (int i = 0; i < 4; i++)
#pragma unroll
        for (int j = 0; j < 4; j++)
#pragma unroll
            for (int r = 0; r < 4; r++) acc[i][j][r] = 0.f;

    loadTile(0, 0);
    cpcommit();

    for (int t = 0; t < NT; ++t) {
        const int cur = t & 1;
        if (t + 1 < NT) {
            loadTile(t + 1, cur ^ 1);
            cpcommit();
            cpwait1();
        } else {
            cpwait0();
        }
        __syncthreads();

        const float* cA = sA[cur];
        const float* cW = sW[cur];
#pragma unroll
        for (int ks = 0; ks < 2; ++ks) {
            uint32_t af[4][4], bf[4][2];
            const int kc = ks * 8 + q;
#pragma unroll
            for (int i = 0; i < 4; i++) {
                const int mr = mw + i * 16 + g;
                if (ACH) {
                    af[i][0] = f2tf(cA[kc * SATSTR + mr]);
                    af[i][1] = f2tf(cA[kc * SATSTR + mr + 8]);
                    af[i][2] = f2tf(cA[(kc + 4) * SATSTR + mr]);
                    af[i][3] = f2tf(cA[(kc + 4) * SATSTR + mr + 8]);
                } else {
                    af[i][0] = f2tf(cA[mr * SASTR + kc]);
                    af[i][1] = f2tf(cA[(mr + 8) * SASTR + kc]);
                    af[i][2] = f2tf(cA[mr * SASTR + kc + 4]);
                    af[i][3] = f2tf(cA[(mr + 8) * SASTR + kc + 4]);
                }
            }
#pragma unroll
            for (int j = 0; j < 4; j++) {
                const int e = nw + j * 8 + g;
                bf[j][0] = f2tf(cW[e * SWSTR + kc]);
                bf[j][1] = f2tf(cW[e * SWSTR + kc + 4]);
            }
#pragma unroll
            for (int i = 0; i < 4; i++)
#pragma unroll
                for (int j = 0; j < 4; j++) mma_tf32(acc[i][j], af[i], bf[j]);
        }
        __syncthreads();
    }

    // epilogue: C[e][m] channel-major: Cout[b*E*S + e*S + s]
    float* Cblk = Cout + (size_t)b * E_ * S_ + (size_t)e0 * S_ + s0;
#pragma unroll
    for (int i = 0; i < 4; i++) {
        const int mr = mw + i * 16 + g;
#pragma unroll
        for (int j = 0; j < 4; j++) {
            const int e = nw + j * 8 + q * 2;
            const float bv0 = __ldg(bias + e0 + e);
            const float bv1 = __ldg(bias + e0 + e + 1);
            Cblk[(size_t)e * S_ + mr] = acc[i][j][0] + bv0;
            Cblk[(size_t)(e + 1) * S_ + mr] = acc[i][j][1] + bv1;
            Cblk[(size_t)e * S_ + mr + 8] = acc[i][j][2] + bv0;
            Cblk[(size_t)(e + 1) * S_ + mr + 8] = acc[i][j][3] + bv1;
        }
    }
}

// ------------------------------- Scan --------------------------------------
// Single read pass: lane owns 16 consecutive steps; 8 carried iterations of
// 512 steps per warp cover S=4096. (c,v) pairs stay in registers.

__device__ __forceinline__ float sigm(float x) { return 1.0f / (1.0f + __expf(-x)); }

__device__ __forceinline__ void step_cv(float gg, float hh, float& c, float& v) {
    const float z = sigm(gg);
    c = 1.0f - z;
    const float gl = (hh >= 0.f) ? (hh + 0.5f) : sigm(hh);
    v = z * gl;
}

// gh: (B,2H,S) channel-major.
// TOKOUT=false -> out (B,H,S) channel-major (coalesced float4 direct)
// TOKOUT=true  -> out (B,S,H) token-major via smem transpose (32B sectors)
template <bool TOKOUT>
__global__ __launch_bounds__(256) void scan_kernel(
    const float* __restrict__ gh, float* __restrict__ out)
{
    __shared__ float stg[2080];   // [lane*65 + t*8 + w] — conflict-free both phases
    const int tid = threadIdx.x, w = tid >> 5, lane = tid & 31;
    const int gw = blockIdx.x * 8 + w;
    const int b = gw >> 10;
    const int h = gw & 1023;
    const int h0 = (blockIdx.x * 8) & 1023;

    const float* gate = gh + ((size_t)b * E_ + h) * S_;
    const float* hid = gate + (size_t)H_ * S_;

    float hprev = 0.5f;

    for (int iter = 0; iter < 8; ++iter) {
        const int sbase = iter * 512 + lane * 16;
        const float4* g4 = (const float4*)(gate + sbase);
        const float4* h4 = (const float4*)(hid + sbase);

        // load 16 steps (8 x float4, MLP=8), build (c,v) pairs in registers
        float c[16], v[16];
        float C = 1.f, V = 0.f;
#pragma unroll
        for (int i = 0; i < 4; i++) {
            const float4 gv = __ldg(g4 + i);
            const float4 hv = __ldg(h4 + i);
            const float* gp = (const float*)&gv;
            const float* hp = (const float*)&hv;
#pragma unroll
            for (int j = 0; j < 4; j++) {
                step_cv(gp[j], hp[j], c[i * 4 + j], v[i * 4 + j]);
                V = __fmaf_rn(c[i * 4 + j], V, v[i * 4 + j]);
                C *= c[i * 4 + j];
            }
        }

        // warp inclusive scan of affine maps
        float Ci = C, Vi = V;
#pragma unroll
        for (int d = 1; d < 32; d <<= 1) {
            const float Cu = __shfl_up_sync(0xffffffffu, Ci, d);
            const float Vu = __shfl_up_sync(0xffffffffu, Vi, d);
            if (lane >= d) { Vi = __fmaf_rn(Ci, Vu, Vi); Ci *= Cu; }
        }
        // carry for next iteration (lane31 inclusive applied to hprev)
        const float C31 = __shfl_sync(0xffffffffu, Ci, 31);
        const float V31 = __shfl_sync(0xffffffffu, Vi, 31);
        // exclusive prefix -> this lane's starting h
        const float Ce = __shfl_up_sync(0xffffffffu, Ci, 1);
        const float Ve = __shfl_up_sync(0xffffffffu, Vi, 1);
        float hcur = (lane == 0) ? hprev : __fmaf_rn(Ce, hprev, Ve);
        hprev = __fmaf_rn(C31, hprev, V31);

        // apply the 16 stored maps
        float hv16[16];
#pragma unroll
        for (int i = 0; i < 16; i++) {
            hcur = __fmaf_rn(c[i], hcur, v[i]);
            hv16[i] = hcur;
        }

        if (!TOKOUT) {
            float4* op = (float4*)(out + (size_t)b * H_ * S_ + (size_t)h * S_ + sbase);
#pragma unroll
            for (int i = 0; i < 4; i++) {
                float4 o;
                o.x = hv16[i * 4 + 0]; o.y = hv16[i * 4 + 1];
                o.z = hv16[i * 4 + 2]; o.w = hv16[i * 4 + 3];
                op[i] = o;
            }
        } else {
            // smem transpose: two sub-chunks of 8 steps
#pragma unroll
            for (int c2 = 0; c2 < 2; ++c2) {
#pragma unroll
                for (int t = 0; t < 8; t++) stg[lane * 65 + t * 8 + w] = hv16[c2 * 8 + t];
                __syncthreads();
#pragma unroll
                for (int i = 0; i < 2; i++) {
                    const int f = i * 256 + tid;
                    const int half = f & 1, t = (f >> 1) & 7, l = f >> 4;
                    const int base = l * 65 + t * 8 + half * 4;
                    float4 o;
                    o.x = stg[base]; o.y = stg[base + 1];
                    o.z = stg[base + 2]; o.w = stg[base + 3];
                    const int s = iter * 512 + l * 16 + c2 * 8 + t;
                    *(float4*)(out + ((size_t)b * S_ + s) * H_ + h0 + half * 4) = o;
                }
                __syncthreads();
            }
        }
    }
}

// ------------------------------ Launch -------------------------------------

extern "C" void kernel_launch(void* const* d_in, const int* in_sizes, int n_in,
                              void* d_out, int out_size)
{
    (void)in_sizes; (void)n_in; (void)out_size;
    const float* x = (const float*)d_in[0];
    const float* W0 = (const float*)d_in[1];
    const float* b0 = (const float*)d_in[2];
    const float* W1 = (const float*)d_in[3];
    const float* b1 = (const float*)d_in[4];
    float* out = (float*)d_out;

    float* gbuf = nullptr;
    float* h1 = nullptr;
    cudaGetSymbolAddress((void**)&gbuf, g_gbuf);
    cudaGetSymbolAddress((void**)&h1, g_h1buf);

    const dim3 gThr(256);
    const dim3 gGrid(E_ / BN, M_ / BM);     // (16, 256)
    const int scanBlocks = (B_ * H_) / 8;   // 1024 blocks, 8 warps each

    gemm_kernel<false><<<gGrid, gThr>>>(x, W0, b0, gbuf);
    scan_kernel<false><<<scanBlocks, 256>>>(gbuf, h1);
    gemm_kernel<true><<<gGrid, gThr>>>(h1, W1, b1, gbuf);
    scan_kernel<true><<<scanBlocks, 256>>>(gbuf, out);
}

// round 6
// speedup vs baseline: 1.2685x; 1.0027x over previous
#include <cuda_runtime.h>
#include <cstdint>
#include <cstddef>

// ---------------------------------------------------------------------------
// MinGRU (2 layers): round(x,W0,W1) -> GEMM0 -> scan0 -> GEMM1 -> scan1
// B=8, S=4096, D=H=1024, E=2H=2048, M=32768, K=1024.
// GEMM: tf32 mma.sync.m16n8k8 (legacy HMMA; sm_103 target has no tcgen05),
//       CTA tile 128x256x32, 8 warps x (64x64), 3-stage cp.async pipeline,
//       operands pre-rounded to tf32 (no cvt in mainloop).
// GEMM out: channel-major (B,2H,S). Scan: warp/channel single-pass affine scan,
//       smem-transposed coalesced writes for the (B,S,H) final output.
// ---------------------------------------------------------------------------

#define B_ 8
#define S_ 4096
#define K_ 1024
#define H_ 1024
#define E_ 2048
#define M_ (B_ * S_)

// scratch (no cudaMalloc allowed)
__device__ float g_gbuf[(size_t)B_ * E_ * S_];    // 268 MB: GEMM out (B,2H,S)
__device__ float g_h1buf[(size_t)B_ * H_ * S_];   // 134 MB: layer-0 h (B,H,S), tf32-rounded
__device__ float g_xr[(size_t)M_ * K_];           // 134 MB: tf32-rounded x
__device__ float g_w0r[(size_t)E_ * K_];          // 8 MB
__device__ float g_w1r[(size_t)E_ * K_];          // 8 MB

// ------------------------------ helpers ------------------------------------

__device__ __forceinline__ float f2tff(float x) {
    float y;
    asm volatile("cvt.rna.tf32.f32 %0, %1;" : "=f"(y) : "f"(x));
    return y;
}
__device__ __forceinline__ void cpasync16(uint32_t dst, const void* src) {
    asm volatile("cp.async.cg.shared.global [%0], [%1], 16;\n" ::"r"(dst), "l"(src));
}
__device__ __forceinline__ void cpcommit() { asm volatile("cp.async.commit_group;\n"); }
__device__ __forceinline__ void cpwait1() { asm volatile("cp.async.wait_group 1;\n"); }

__device__ __forceinline__ void mma_tf32(float* c, const uint32_t* a, const uint32_t* b) {
    asm volatile(
        "mma.sync.aligned.m16n8k8.row.col.f32.tf32.tf32.f32 "
        "{%0,%1,%2,%3}, {%4,%5,%6,%7}, {%8,%9}, {%0,%1,%2,%3};\n"
        : "+f"(c[0]), "+f"(c[1]), "+f"(c[2]), "+f"(c[3])
        : "r"(a[0]), "r"(a[1]), "r"(a[2]), "r"(a[3]), "r"(b[0]), "r"(b[1]));
}

// --------------------------- rounding transform ----------------------------

__global__ void round_kernel(const float* __restrict__ in, float* __restrict__ out) {
    const size_t i = ((size_t)blockIdx.x * 256 + threadIdx.x) * 4;
    float4 v = *(const float4*)(in + i);
    v.x = f2tff(v.x); v.y = f2tff(v.y); v.z = f2tff(v.z); v.w = f2tff(v.w);
    *(float4*)(out + i) = v;
}

// ------------------------------- GEMM --------------------------------------
// CTA 128(M) x 256(N) x BK=32; 8 warps, each 64x64 (acc[4][8][4]).

#define BM 128
#define BN 256
#define BK 32
#define SAS 36        // token-major A smem stride ([m][k])
#define SATS 136      // channel-major A smem stride ([k][m])
#define SWS 36        // W smem stride ([e][k])
#define ASZ 4608      // floats per A stage (max of 128*36, 32*136)
#define WSZ 9216      // floats per W stage (256*36)
#define STAGES 3
#define NT (K_ / BK)  // 32 k-tiles
#define SMEM_GEMM (STAGES * (ASZ + WSZ) * 4)   // 165888 B

// ACH=false: A token-major (M,K). ACH=true: A channel-major (B,K,S).
template <bool ACH>
__global__ __launch_bounds__(256, 1) void gemm_kernel(
    const float* __restrict__ A, const float* __restrict__ W,
    const float* __restrict__ bias, float* __restrict__ Cout)
{
    extern __shared__ float smem[];
    float* sA = smem;                 // STAGES * ASZ
    float* sW = smem + STAGES * ASZ;  // STAGES * WSZ

    const int tid = threadIdx.x;
    const int warp = tid >> 5, lane = tid & 31;
    const int g = lane >> 2, q = lane & 3;
    const int mw = (warp & 1) * 64;
    const int nw = (warp >> 1) * 64;

    const int m0 = blockIdx.y * BM;
    const int b = m0 >> 12;
    const int s0 = m0 & (S_ - 1);
    const int e0 = blockIdx.x * BN;

    const float* Ablk;
    if (ACH) Ablk = A + (size_t)b * K_ * S_ + s0;   // + k*S_ + m_local
    else     Ablk = A + (size_t)m0 * K_;            // + m_local*K_ + k
    const float* Wblk = W + (size_t)e0 * K_;

    const uint32_t saAddr = (uint32_t)__cvta_generic_to_shared(sA);
    const uint32_t swAddr = (uint32_t)__cvta_generic_to_shared(sW);

    auto loadTile = [&](int kt, int st) {
#pragma unroll
        for (int it = 0; it < 4; ++it) {
            const int id = tid + it * 256;        // 1024 x 16B chunks
            if (ACH) {
                const int r = id >> 5, c = (id & 31) * 4;   // r=k row, c=m col
                cpasync16(saAddr + (uint32_t)(st * ASZ + r * SATS + c) * 4,
                          Ablk + (size_t)(kt * BK + r) * S_ + c);
            } else {
                const int r = id >> 3, c = (id & 7) * 4;    // r=m row, c=k col
                cpasync16(saAddr + (uint32_t)(st * ASZ + r * SAS + c) * 4,
                          Ablk + (size_t)r * K_ + kt * BK + c);
            }
        }
#pragma unroll
        for (int it = 0; it < 8; ++it) {
            const int id = tid + it * 256;        // 2048 x 16B chunks
            const int r = id >> 3, c = (id & 7) * 4;
            cpasync16(swAddr + (uint32_t)(st * WSZ + r * SWS + c) * 4,
                      Wblk + (size_t)r * K_ + kt * BK + c);
        }
    };

    float acc[4][8][4];
#pragma unroll
    for (int i = 0; i < 4; i++)
#pragma unroll
        for (int j = 0; j < 8; j++)
#pragma unroll
            for (int r = 0; r < 4; r++) acc[i][j][r] = 0.f;

    loadTile(0, 0); cpcommit();
    loadTile(1, 1); cpcommit();

    for (int t = 0; t < NT; ++t) {
        cpwait1();
        __syncthreads();
        if (t + 2 < NT) { loadTile(t + 2, (t + 2) % 3); cpcommit(); }

        const float* cA = sA + (t % 3) * ASZ;
        const float* cW = sW + (t % 3) * WSZ;
#pragma unroll
        for (int ks = 0; ks < 4; ++ks) {
            const int kc = ks * 8 + q;
            uint32_t af[4][4], bf[8][2];
#pragma unroll
            for (int i = 0; i < 4; i++) {
                const int mr = mw + i * 16 + g;
                if (ACH) {
                    af[i][0] = __float_as_uint(cA[kc * SATS + mr]);
                    af[i][1] = __float_as_uint(cA[kc * SATS + mr + 8]);
                    af[i][2] = __float_as_uint(cA[(kc + 4) * SATS + mr]);
                    af[i][3] = __float_as_uint(cA[(kc + 4) * SATS + mr + 8]);
                } else {
                    af[i][0] = __float_as_uint(cA[mr * SAS + kc]);
                    af[i][1] = __float_as_uint(cA[(mr + 8) * SAS + kc]);
                    af[i][2] = __float_as_uint(cA[mr * SAS + kc + 4]);
                    af[i][3] = __float_as_uint(cA[(mr + 8) * SAS + kc + 4]);
                }
            }
#pragma unroll
            for (int j = 0; j < 8; j++) {
                const int e = nw + j * 8 + g;
                bf[j][0] = __float_as_uint(cW[e * SWS + kc]);
                bf[j][1] = __float_as_uint(cW[e * SWS + kc + 4]);
            }
#pragma unroll
            for (int i = 0; i < 4; i++)
#pragma unroll
                for (int j = 0; j < 8; j++) mma_tf32(acc[i][j], af[i], bf[j]);
        }
        __syncthreads();
    }

    // epilogue: channel-major Cout[b*E*S + e*S + s]; 8 consecutive m per (e)
    float* Cblk = Cout + (size_t)b * E_ * S_ + (size_t)e0 * S_ + s0;
#pragma unroll
    for (int i = 0; i < 4; i++) {
        const int mr = mw + i * 16 + g;
#pragma unroll
        for (int j = 0; j < 8; j++) {
            const int e = nw + j * 8 + q * 2;
            const float bv0 = __ldg(bias + e0 + e);
            const float bv1 = __ldg(bias + e0 + e + 1);
            Cblk[(size_t)e * S_ + mr] = acc[i][j][0] + bv0;
            Cblk[(size_t)(e + 1) * S_ + mr] = acc[i][j][1] + bv1;
            Cblk[(size_t)e * S_ + mr + 8] = acc[i][j][2] + bv0;
            Cblk[(size_t)(e + 1) * S_ + mr + 8] = acc[i][j][3] + bv1;
        }
    }
}

// ------------------------------- Scan --------------------------------------

__device__ __forceinline__ float sigm(float x) { return 1.0f / (1.0f + __expf(-x)); }
__device__ __forceinline__ void step_cv(float gg, float hh, float& c, float& v) {
    const float z = sigm(gg);
    c = 1.0f - z;
    const float gl = (hh >= 0.f) ? (hh + 0.5f) : sigm(hh);
    v = z * gl;
}

// gh: (B,2H,S). TOKOUT=false -> (B,H,S) tf32-rounded (feeds GEMM1);
// TOKOUT=true -> (B,S,H) via smem transpose.
template <bool TOKOUT>
__global__ __launch_bounds__(256) void scan_kernel(
    const float* __restrict__ gh, float* __restrict__ out)
{
    __shared__ float stg[2080];
    const int tid = threadIdx.x, w = tid >> 5, lane = tid & 31;
    const int gw = blockIdx.x * 8 + w;
    const int b = gw >> 10;
    const int h = gw & 1023;
    const int h0 = (blockIdx.x * 8) & 1023;

    const float* gate = gh + ((size_t)b * E_ + h) * S_;
    const float* hid = gate + (size_t)H_ * S_;

    float hprev = 0.5f;

    for (int iter = 0; iter < 8; ++iter) {
        const int sbase = iter * 512 + lane * 16;
        const float4* g4 = (const float4*)(gate + sbase);
        const float4* h4 = (const float4*)(hid + sbase);

        float c[16], v[16];
        float C = 1.f, V = 0.f;
#pragma unroll
        for (int i = 0; i < 4; i++) {
            const float4 gv = __ldg(g4 + i);
            const float4 hv = __ldg(h4 + i);
            const float* gp = (const float*)&gv;
            const float* hp = (const float*)&hv;
#pragma unroll
            for (int j = 0; j < 4; j++) {
                step_cv(gp[j], hp[j], c[i * 4 + j], v[i * 4 + j]);
                V = __fmaf_rn(c[i * 4 + j], V, v[i * 4 + j]);
                C *= c[i * 4 + j];
            }
        }

        float Ci = C, Vi = V;
#pragma unroll
        for (int d = 1; d < 32; d <<= 1) {
            const float Cu = __shfl_up_sync(0xffffffffu, Ci, d);
            const float Vu = __shfl_up_sync(0xffffffffu, Vi, d);
            if (lane >= d) { Vi = __fmaf_rn(Ci, Vu, Vi); Ci *= Cu; }
        }
        const float C31 = __shfl_sync(0xffffffffu, Ci, 31);
        const float V31 = __shfl_sync(0xffffffffu, Vi, 31);
        const float Ce = __shfl_up_sync(0xffffffffu, Ci, 1);
        const float Ve = __shfl_up_sync(0xffffffffu, Vi, 1);
        float hcur = (lane == 0) ? hprev : __fmaf_rn(Ce, hprev, Ve);
        hprev = __fmaf_rn(C31, hprev, V31);

        float hv16[16];
#pragma unroll
        for (int i = 0; i < 16; i++) {
            hcur = __fmaf_rn(c[i], hcur, v[i]);
            hv16[i] = hcur;
        }

        if (!TOKOUT) {
            float4* op = (float4*)(out + (size_t)b * H_ * S_ + (size_t)h * S_ + sbase);
#pragma unroll
            for (int i = 0; i < 4; i++) {
                float4 o;
                o.x = f2tff(hv16[i * 4 + 0]); o.y = f2tff(hv16[i * 4 + 1]);
                o.z = f2tff(hv16[i * 4 + 2]); o.w = f2tff(hv16[i * 4 + 3]);
                op[i] = o;
            }
        } else {
#pragma unroll
            for (int c2 = 0; c2 < 2; ++c2) {
#pragma unroll
                for (int t = 0; t < 8; t++) stg[lane * 65 + t * 8 + w] = hv16[c2 * 8 + t];
                __syncthreads();
#pragma unroll
                for (int i = 0; i < 2; i++) {
                    const int f = i * 256 + tid;
                    const int half = f & 1, t = (f >> 1) & 7, l = f >> 4;
                    const int base = l * 65 + t * 8 + half * 4;
                    float4 o;
                    o.x = stg[base]; o.y = stg[base + 1];
                    o.z = stg[base + 2]; o.w = stg[base + 3];
                    const int s = iter * 512 + l * 16 + c2 * 8 + t;
                    *(float4*)(out + ((size_t)b * S_ + s) * H_ + h0 + half * 4) = o;
                }
                __syncthreads();
            }
        }
    }
}

// ------------------------------ Launch -------------------------------------

extern "C" void kernel_launch(void* const* d_in, const int* in_sizes, int n_in,
                              void* d_out, int out_size)
{
    (void)in_sizes; (void)n_in; (void)out_size;
    const float* x = (const float*)d_in[0];
    const float* W0 = (const float*)d_in[1];
    const float* b0 = (const float*)d_in[2];
    const float* W1 = (const float*)d_in[3];
    const float* b1 = (const float*)d_in[4];
    float* out = (float*)d_out;

    float *gbuf, *h1, *xr, *w0r, *w1r;
    cudaGetSymbolAddress((void**)&gbuf, g_gbuf);
    cudaGetSymbolAddress((void**)&h1, g_h1buf);
    cudaGetSymbolAddress((void**)&xr, g_xr);
    cudaGetSymbolAddress((void**)&w0r, g_w0r);
    cudaGetSymbolAddress((void**)&w1r, g_w1r);

    cudaFuncSetAttribute(gemm_kernel<false>,
                         cudaFuncAttributeMaxDynamicSharedMemorySize, SMEM_GEMM);
    cudaFuncSetAttribute(gemm_kernel<true>,
                         cudaFuncAttributeMaxDynamicSharedMemorySize, SMEM_GEMM);

    round_kernel<<<(int)((size_t)M_ * K_ / 1024), 256>>>(x, xr);
    round_kernel<<<(int)((size_t)E_ * K_ / 1024), 256>>>(W0, w0r);
    round_kernel<<<(int)((size_t)E_ * K_ / 1024), 256>>>(W1, w1r);

    const dim3 gGrid(E_ / BN, M_ / BM);     // (8, 256)
    const int scanBlocks = (B_ * H_) / 8;   // 1024

    gemm_kernel<false><<<gGrid, 256, SMEM_GEMM>>>(xr, w0r, b0, gbuf);
    scan_kernel<false><<<scanBlocks, 256>>>(gbuf, h1);
    gemm_kernel<true><<<gGrid, 256, SMEM_GEMM>>>(h1, w1r, b1, gbuf);
    scan_kernel<true><<<scanBlocks, 256>>>(gbuf, out);
}

// round 8
// speedup vs baseline: 2.4792x; 1.9544x over previous
#include <cuda_runtime.h>
#include <cuda_fp16.h>
#include <cstdint>
#include <cstddef>

// ---------------------------------------------------------------------------
// MinGRU (2 layers): tohalf(x,W0,W1) -> GEMM0 -> scan0 -> GEMM1 -> scan1
// B=8, S=4096, D=H=1024, E=2H=2048, M=32768, K=1024.
// GEMM: fp16 mma.sync.m16n8k16 (f32 accum; fp16 mantissa == tf32 mantissa),
//       CTA 128x256, BK=64, 3-stage cp.async, ONE barrier per k-tile,
//       ldmatrix.x4 (+.trans for channel-major A) with xor-swizzled smem.
// GEMM out: channel-major (B,2H,S) f32. Scan: warp/channel single-pass affine
//       scan; scan0 emits half (B,H,S) feeding GEMM1; scan1 emits f32 (B,S,H)
//       via smem transpose.
// ---------------------------------------------------------------------------

#define B_ 8
#define S_ 4096
#define K_ 1024
#define H_ 1024
#define E_ 2048
#define M_ (B_ * S_)

// scratch (no cudaMalloc allowed)
__device__ float g_gbuf[(size_t)B_ * E_ * S_];     // 268 MB GEMM out (B,2H,S)
__device__ __half g_h1h[(size_t)B_ * H_ * S_];     // 67 MB layer-0 h, half (B,H,S)
__device__ __half g_xh[(size_t)M_ * K_];           // 67 MB x in half
__device__ __half g_w0h[(size_t)E_ * K_];          // 4 MB
__device__ __half g_w1h[(size_t)E_ * K_];          // 4 MB

// ------------------------------ helpers ------------------------------------

__device__ __forceinline__ void cpasync16(uint32_t dst, const void* src) {
    asm volatile("cp.async.cg.shared.global [%0], [%1], 16;\n" ::"r"(dst), "l"(src));
}
__device__ __forceinline__ void cpcommit() { asm volatile("cp.async.commit_group;\n"); }
__device__ __forceinline__ void cpwait1() { asm volatile("cp.async.wait_group 1;\n"); }
__device__ __forceinline__ void cpwait0() { asm volatile("cp.async.wait_group 0;\n"); }

__device__ __forceinline__ void ldsm4(uint32_t* d, uint32_t addr) {
    asm volatile("ldmatrix.sync.aligned.m8n8.x4.shared.b16 {%0,%1,%2,%3}, [%4];"
                 : "=r"(d[0]), "=r"(d[1]), "=r"(d[2]), "=r"(d[3]) : "r"(addr));
}
__device__ __forceinline__ void ldsm4t(uint32_t* d, uint32_t addr) {
    asm volatile("ldmatrix.sync.aligned.m8n8.x4.trans.shared.b16 {%0,%1,%2,%3}, [%4];"
                 : "=r"(d[0]), "=r"(d[1]), "=r"(d[2]), "=r"(d[3]) : "r"(addr));
}
__device__ __forceinline__ void mma_f16(float* c, const uint32_t* a, const uint32_t* b) {
    asm volatile(
        "mma.sync.aligned.m16n8k16.row.col.f32.f16.f16.f32 "
        "{%0,%1,%2,%3}, {%4,%5,%6,%7}, {%8,%9}, {%0,%1,%2,%3};\n"
        : "+f"(c[0]), "+f"(c[1]), "+f"(c[2]), "+f"(c[3])
        : "r"(a[0]), "r"(a[1]), "r"(a[2]), "r"(a[3]), "r"(b[0]), "r"(b[1]));
}

// --------------------------- f32 -> f16 transform --------------------------

__global__ void tohalf_kernel(const float* __restrict__ in, __half* __restrict__ out) {
    const size_t i = ((size_t)blockIdx.x * 256 + threadIdx.x) * 4;
    const float4 v = *(const float4*)(in + i);
    const __half2 h0 = __floats2half2_rn(v.x, v.y);
    const __half2 h1 = __floats2half2_rn(v.z, v.w);
    uint2 u;
    u.x = *(const uint32_t*)&h0;
    u.y = *(const uint32_t*)&h1;
    *(uint2*)(out + i) = u;
}

// ------------------------------- GEMM --------------------------------------
// CTA 128(M) x 256(N), BK=64; 8 warps (2x4), warp tile 64x64.
// smem (half): A stage 128x64 = 16KB (or 64k x 128m for ACH), W stage 256x64 = 32KB.
// Swizzle: 16B chunk c of row r stored at chunk c ^ (r & 7).

#define BM 128
#define BN 256
#define BK 64
#define NTT (K_ / BK)      // 16 k-tiles
#define ASTG 16384
#define WSTG 32768
#define SMEM_GEMM (3 * (ASTG + WSTG))   // 147456 B

// ACH=false: A token-major (M,K) half. ACH=true: A channel-major (B,K,S) half.
template <bool ACH>
__global__ __launch_bounds__(256, 1) void gemm_kernel(
    const __half* __restrict__ A, const __half* __restrict__ W,
    const float* __restrict__ bias, float* __restrict__ Cout)
{
    extern __shared__ char smem[];
    const uint32_t sb = (uint32_t)__cvta_generic_to_shared(smem);

    const int tid = threadIdx.x;
    const int warp = tid >> 5, lane = tid & 31;
    const int g = lane >> 2, q = lane & 3;
    const int tt = lane >> 3, r = lane & 7;   // ldmatrix tile id / row-in-tile
    const int mw = (warp & 1) * 64;
    const int nw = (warp >> 1) * 64;

    const int m0 = blockIdx.y * BM;
    const int b = m0 >> 12;
    const int s0 = m0 & (S_ - 1);
    const int e0 = blockIdx.x * BN;

    const __half* Ablk;
    if (ACH) Ablk = A + (size_t)b * K_ * S_ + s0;   // + k*S_ + m_local
    else     Ablk = A + (size_t)m0 * K_;            // + m_local*K_ + k
    const __half* Wblk = W + (size_t)e0 * K_;

    auto loadTile = [&](int kt, int st) {
        const uint32_t aBase = sb + st * ASTG;
        const uint32_t wBase = sb + 3 * ASTG + st * WSTG;
#pragma unroll
        for (int it = 0; it < 4; ++it) {            // A: 1024 x 16B
            const int id = tid + it * 256;
            if (ACH) {
                const int rr = id >> 4, c = id & 15;    // 64 k-rows x 16 chunks
                cpasync16(aBase + rr * 256 + ((c ^ (rr & 7)) * 16),
                          Ablk + (size_t)(kt * BK + rr) * S_ + c * 8);
            } else {
                const int m = id >> 3, c = id & 7;      // 128 m-rows x 8 chunks
                cpasync16(aBase + m * 128 + ((c ^ (m & 7)) * 16),
                          Ablk + (size_t)m * K_ + kt * BK + c * 8);
            }
        }
#pragma unroll
        for (int it = 0; it < 8; ++it) {            // W: 2048 x 16B
            const int id = tid + it * 256;
            const int e = id >> 3, c = id & 7;
            cpasync16(wBase + e * 128 + ((c ^ (e & 7)) * 16),
                      Wblk + (size_t)e * K_ + kt * BK + c * 8);
        }
    };

    float acc[4][8][4];
#pragma unroll
    for (int i = 0; i < 4; i++)
#pragma unroll
        for (int j = 0; j < 8; j++)
#pragma unroll
            for (int x = 0; x < 4; x++) acc[i][j][x] = 0.f;

    loadTile(0, 0); cpcommit();
    loadTile(1, 1); cpcommit();

    for (int t = 0; t < NTT; ++t) {
        if (t + 1 < NTT) cpwait1(); else cpwait0();   // tile t fully landed
        __syncthreads();
        if (t + 2 < NTT) { loadTile(t + 2, (t + 2) % 3); cpcommit(); }

        const uint32_t aB = sb + (t % 3) * ASTG;
        const uint32_t wB = sb + 3 * ASTG + (t % 3) * WSTG;

#pragma unroll
        for (int s = 0; s < 4; ++s) {               // 4 x k16 per tile
            uint32_t af[4][4], bf[4][4];
#pragma unroll
            for (int i = 0; i < 4; i++) {
                if (ACH) {
                    const int krow = s * 16 + (tt >> 1) * 8 + r;
                    const int mch = ((mw + i * 16) >> 3) + (tt & 1);
                    ldsm4t(af[i], aB + krow * 256 + ((mch ^ r) * 16));
                } else {
                    const int row = mw + i * 16 + (tt & 1) * 8 + r;
                    const int kch = s * 2 + (tt >> 1);
                    ldsm4(af[i], aB + row * 128 + ((kch ^ r) * 16));
                }
            }
#pragma unroll
            for (int jp = 0; jp < 4; jp++) {
                const int e = nw + jp * 16 + (tt >> 1) * 8 + r;
                const int kch = s * 2 + (tt & 1);
                ldsm4(bf[jp], wB + e * 128 + ((kch ^ r) * 16));
            }
#pragma unroll
            for (int i = 0; i < 4; i++)
#pragma unroll
                for (int j = 0; j < 8; j++)
                    mma_f16(acc[i][j], af[i], &bf[j >> 1][(j & 1) * 2]);
        }
    }

    // epilogue: channel-major Cout[b*E*S + e*S + s] + bias
    float* Cblk = Cout + (size_t)b * E_ * S_ + (size_t)e0 * S_ + s0;
#pragma unroll
    for (int i = 0; i < 4; i++) {
        const int mr = mw + i * 16 + g;
#pragma unroll
        for (int j = 0; j < 8; j++) {
            const int e = nw + j * 8 + q * 2;
            const float bv0 = __ldg(bias + e0 + e);
            const float bv1 = __ldg(bias + e0 + e + 1);
            Cblk[(size_t)e * S_ + mr] = acc[i][j][0] + bv0;
            Cblk[(size_t)(e + 1) * S_ + mr] = acc[i][j][1] + bv1;
            Cblk[(size_t)e * S_ + mr + 8] = acc[i][j][2] + bv0;
            Cblk[(size_t)(e + 1) * S_ + mr + 8] = acc[i][j][3] + bv1;
        }
    }
}

// ------------------------------- Scan --------------------------------------

__device__ __forceinline__ float sigm(float x) { return 1.0f / (1.0f + __expf(-x)); }
__device__ __forceinline__ void step_cv(float gg, float hh, float& c, float& v) {
    const float z = sigm(gg);
    c = 1.0f - z;
    const float gl = (hh >= 0.f) ? (hh + 0.5f) : sigm(hh);
    v = z * gl;
}

// gh: (B,2H,S) f32. TOKOUT=false -> half (B,H,S) (feeds GEMM1);
// TOKOUT=true -> f32 (B,S,H) via smem transpose.
template <bool TOKOUT>
__global__ __launch_bounds__(256) void scan_kernel(
    const float* __restrict__ gh, void* __restrict__ outv)
{
    __shared__ float stg[2080];
    const int tid = threadIdx.x, w = tid >> 5, lane = tid & 31;
    const int gw = blockIdx.x * 8 + w;
    const int b = gw >> 10;
    const int h = gw & 1023;
    const int h0 = (blockIdx.x * 8) & 1023;

    const float* gate = gh + ((size_t)b * E_ + h) * S_;
    const float* hid = gate + (size_t)H_ * S_;

    float hprev = 0.5f;

    for (int iter = 0; iter < 8; ++iter) {
        const int sbase = iter * 512 + lane * 16;
        const float4* g4 = (const float4*)(gate + sbase);
        const float4* h4 = (const float4*)(hid + sbase);

        float c[16], v[16];
        float C = 1.f, V = 0.f;
#pragma unroll
        for (int i = 0; i < 4; i++) {
            const float4 gv = __ldg(g4 + i);
            const float4 hv = __ldg(h4 + i);
            const float* gp = (const float*)&gv;
            const float* hp = (const float*)&hv;
#pragma unroll
            for (int j = 0; j < 4; j++) {
                step_cv(gp[j], hp[j], c[i * 4 + j], v[i * 4 + j]);
                V = __fmaf_rn(c[i * 4 + j], V, v[i * 4 + j]);
                C *= c[i * 4 + j];
            }
        }

        float Ci = C, Vi = V;
#pragma unroll
        for (int d = 1; d < 32; d <<= 1) {
            const float Cu = __shfl_up_sync(0xffffffffu, Ci, d);
            const float Vu = __shfl_up_sync(0xffffffffu, Vi, d);
            if (lane >= d) { Vi = __fmaf_rn(Ci, Vu, Vi); Ci *= Cu; }
        }
        const float C31 = __shfl_sync(0xffffffffu, Ci, 31);
        const float V31 = __shfl_sync(0xffffffffu, Vi, 31);
        const float Ce = __shfl_up_sync(0xffffffffu, Ci, 1);
        const float Ve = __shfl_up_sync(0xffffffffu, Vi, 1);
        float hcur = (lane == 0) ? hprev : __fmaf_rn(Ce, hprev, Ve);
        hprev = __fmaf_rn(C31, hprev, V31);

        float hv16[16];
#pragma unroll
        for (int i = 0; i < 16; i++) {
            hcur = __fmaf_rn(c[i], hcur, v[i]);
            hv16[i] = hcur;
        }

        if (!TOKOUT) {
            __half* outh = (__half*)outv + (size_t)b * H_ * S_ + (size_t)h * S_ + sbase;
            uint32_t u[8];
#pragma unroll
            for (int i = 0; i < 8; i++) {
                const __half2 h2 = __floats2half2_rn(hv16[2 * i], hv16[2 * i + 1]);
                u[i] = *(const uint32_t*)&h2;
            }
            ((uint4*)outh)[0] = make_uint4(u[0], u[1], u[2], u[3]);
            ((uint4*)outh)[1] = make_uint4(u[4], u[5], u[6], u[7]);
        } else {
            float* out = (float*)outv;
#pragma unroll
            for (int c2 = 0; c2 < 2; ++c2) {
#pragma unroll
                for (int t = 0; t < 8; t++) stg[lane * 65 + t * 8 + w] = hv16[c2 * 8 + t];
                __syncthreads();
#pragma unroll
                for (int i = 0; i < 2; i++) {
                    const int f = i * 256 + tid;
                    const int half_ = f & 1, t = (f >> 1) & 7, l = f >> 4;
                    const int base = l * 65 + t * 8 + half_ * 4;
                    float4 o;
                    o.x = stg[base]; o.y = stg[base + 1];
                    o.z = stg[base + 2]; o.w = stg[base + 3];
                    const int s = iter * 512 + l * 16 + c2 * 8 + t;
                    *(float4*)(out + ((size_t)b * S_ + s) * H_ + h0 + half_ * 4) = o;
                }
                __syncthreads();
            }
        }
    }
}

// ------------------------------ Launch -------------------------------------

extern "C" void kernel_launch(void* const* d_in, const int* in_sizes, int n_in,
                              void* d_out, int out_size)
{
    (void)in_sizes; (void)n_in; (void)out_size;
    const float* x = (const float*)d_in[0];
    const float* W0 = (const float*)d_in[1];
    const float* b0 = (const float*)d_in[2];
    const float* W1 = (const float*)d_in[3];
    const float* b1 = (const float*)d_in[4];
    float* out = (float*)d_out;

    float* gbuf;
    __half *h1h, *xh, *w0h, *w1h;
    cudaGetSymbolAddress((void**)&gbuf, g_gbuf);
    cudaGetSymbolAddress((void**)&h1h, g_h1h);
    cudaGetSymbolAddress((void**)&xh, g_xh);
    cudaGetSymbolAddress((void**)&w0h, g_w0h);
    cudaGetSymbolAddress((void**)&w1h, g_w1h);

    cudaFuncSetAttribute(gemm_kernel<false>,
                         cudaFuncAttributeMaxDynamicSharedMemorySize, SMEM_GEMM);
    cudaFuncSetAttribute(gemm_kernel<true>,
                         cudaFuncAttributeMaxDynamicSharedMemorySize, SMEM_GEMM);

    tohalf_kernel<<<(int)((size_t)M_ * K_ / 1024), 256>>>(x, xh);
    tohalf_kernel<<<(int)((size_t)E_ * K_ / 1024), 256>>>(W0, w0h);
    tohalf_kernel<<<(int)((size_t)E_ * K_ / 1024), 256>>>(W1, w1h);

    const dim3 gGrid(E_ / BN, M_ / BM);     // (8, 256)
    const int scanBlocks = (B_ * H_) / 8;   // 1024

    gemm_kernel<false><<<gGrid, 256, SMEM_GEMM>>>(xh, w0h, b0, gbuf);
    scan_kernel<false><<<scanBlocks, 256>>>(gbuf, h1h);
    gemm_kernel<true><<<gGrid, 256, SMEM_GEMM>>>(h1h, w1h, b1, gbuf);
    scan_kernel<true><<<scanBlocks, 256>>>(gbuf, out);
}

// round 9
// speedup vs baseline: 2.7748x; 1.1192x over previous
#include <cuda_runtime.h>
#include <cuda_fp16.h>
#include <cstdint>
#include <cstddef>

// ---------------------------------------------------------------------------
// MinGRU (2 layers): tohalf(x,W0,W1) -> GEMM0 -> scan0 -> GEMM1 -> scan1
// B=8, S=4096, D=H=1024, E=2H=2048, M=32768, K=1024.
// GEMM: fp16 mma.sync.m16n8k16 (f32 accum), CTA 128x128 / 4 warps (64x64 each),
//       BK=64, 3-stage cp.async, ldmatrix + xor swizzle, 2 CTAs/SM for overlap.
// GEMM out: channel-major (B,2H,S) f32. Scan: warp/channel single-pass affine
//       scan; scan0 emits half (B,H,S) feeding GEMM1; scan1 emits f32 (B,S,H)
//       via smem transpose.
// ---------------------------------------------------------------------------

#define B_ 8
#define S_ 4096
#define K_ 1024
#define H_ 1024
#define E_ 2048
#define M_ (B_ * S_)

// scratch (no cudaMalloc allowed)
__device__ float g_gbuf[(size_t)B_ * E_ * S_];     // 268 MB GEMM out (B,2H,S)
__device__ __half g_h1h[(size_t)B_ * H_ * S_];     // 67 MB layer-0 h, half (B,H,S)
__device__ __half g_xh[(size_t)M_ * K_];           // 67 MB x in half
__device__ __half g_w0h[(size_t)E_ * K_];          // 4 MB
__device__ __half g_w1h[(size_t)E_ * K_];          // 4 MB

// ------------------------------ helpers ------------------------------------

__device__ __forceinline__ void cpasync16(uint32_t dst, const void* src) {
    asm volatile("cp.async.cg.shared.global [%0], [%1], 16;\n" ::"r"(dst), "l"(src));
}
__device__ __forceinline__ void cpcommit() { asm volatile("cp.async.commit_group;\n"); }
__device__ __forceinline__ void cpwait1() { asm volatile("cp.async.wait_group 1;\n"); }
__device__ __forceinline__ void cpwait0() { asm volatile("cp.async.wait_group 0;\n"); }

__device__ __forceinline__ void ldsm4(uint32_t* d, uint32_t addr) {
    asm volatile("ldmatrix.sync.aligned.m8n8.x4.shared.b16 {%0,%1,%2,%3}, [%4];"
                 : "=r"(d[0]), "=r"(d[1]), "=r"(d[2]), "=r"(d[3]) : "r"(addr));
}
__device__ __forceinline__ void ldsm4t(uint32_t* d, uint32_t addr) {
    asm volatile("ldmatrix.sync.aligned.m8n8.x4.trans.shared.b16 {%0,%1,%2,%3}, [%4];"
                 : "=r"(d[0]), "=r"(d[1]), "=r"(d[2]), "=r"(d[3]) : "r"(addr));
}
__device__ __forceinline__ void mma_f16(float* c, const uint32_t* a, const uint32_t* b) {
    asm volatile(
        "mma.sync.aligned.m16n8k16.row.col.f32.f16.f16.f32 "
        "{%0,%1,%2,%3}, {%4,%5,%6,%7}, {%8,%9}, {%0,%1,%2,%3};\n"
        : "+f"(c[0]), "+f"(c[1]), "+f"(c[2]), "+f"(c[3])
        : "r"(a[0]), "r"(a[1]), "r"(a[2]), "r"(a[3]), "r"(b[0]), "r"(b[1]));
}

// --------------------------- f32 -> f16 transform --------------------------

__global__ void tohalf_kernel(const float* __restrict__ in, __half* __restrict__ out) {
    const size_t i = ((size_t)blockIdx.x * 256 + threadIdx.x) * 4;
    const float4 v = *(const float4*)(in + i);
    const __half2 h0 = __floats2half2_rn(v.x, v.y);
    const __half2 h1 = __floats2half2_rn(v.z, v.w);
    uint2 u;
    u.x = *(const uint32_t*)&h0;
    u.y = *(const uint32_t*)&h1;
    *(uint2*)(out + i) = u;
}

// ------------------------------- GEMM --------------------------------------
// CTA 128(M) x 128(N), BK=64; 4 warps (2x2), warp tile 64x64; 2 CTAs/SM.
// smem (half): A stage 16KB, W stage 16KB, 3 stages = 96KB.
// Swizzle: 16B chunk c of row r stored at chunk c ^ (r & 7).

#define BM 128
#define BN 128
#define BK 64
#define NTT (K_ / BK)      // 16 k-tiles
#define ASTG 16384
#define WSTG 16384
#define SMEM_GEMM (3 * (ASTG + WSTG))   // 98304 B

// ACH=false: A token-major (M,K) half. ACH=true: A channel-major (B,K,S) half.
template <bool ACH>
__global__ __launch_bounds__(128, 2) void gemm_kernel(
    const __half* __restrict__ A, const __half* __restrict__ W,
    const float* __restrict__ bias, float* __restrict__ Cout)
{
    extern __shared__ char smem[];
    const uint32_t sb = (uint32_t)__cvta_generic_to_shared(smem);

    const int tid = threadIdx.x;
    const int warp = tid >> 5, lane = tid & 31;
    const int g = lane >> 2, q = lane & 3;
    const int tt = lane >> 3, r = lane & 7;   // ldmatrix tile id / row-in-tile
    const int mw = (warp & 1) * 64;
    const int nw = (warp >> 1) * 64;

    const int m0 = blockIdx.y * BM;
    const int b = m0 >> 12;
    const int s0 = m0 & (S_ - 1);
    const int e0 = blockIdx.x * BN;

    const __half* Ablk;
    if (ACH) Ablk = A + (size_t)b * K_ * S_ + s0;   // + k*S_ + m_local
    else     Ablk = A + (size_t)m0 * K_;            // + m_local*K_ + k
    const __half* Wblk = W + (size_t)e0 * K_;

    auto loadTile = [&](int kt, int st) {
        const uint32_t aBase = sb + st * ASTG;
        const uint32_t wBase = sb + 3 * ASTG + st * WSTG;
#pragma unroll
        for (int it = 0; it < 8; ++it) {            // A: 1024 x 16B
            const int id = tid + it * 128;
            if (ACH) {
                const int rr = id >> 4, c = id & 15;    // 64 k-rows x 16 chunks
                cpasync16(aBase + rr * 256 + ((c ^ (rr & 7)) * 16),
                          Ablk + (size_t)(kt * BK + rr) * S_ + c * 8);
            } else {
                const int m = id >> 3, c = id & 7;      // 128 m-rows x 8 chunks
                cpasync16(aBase + m * 128 + ((c ^ (m & 7)) * 16),
                          Ablk + (size_t)m * K_ + kt * BK + c * 8);
            }
        }
#pragma unroll
        for (int it = 0; it < 8; ++it) {            // W: 1024 x 16B
            const int id = tid + it * 128;
            const int e = id >> 3, c = id & 7;
            cpasync16(wBase + e * 128 + ((c ^ (e & 7)) * 16),
                      Wblk + (size_t)e * K_ + kt * BK + c * 8);
        }
    };

    float acc[4][8][4];
#pragma unroll
    for (int i = 0; i < 4; i++)
#pragma unroll
        for (int j = 0; j < 8; j++)
#pragma unroll
            for (int x = 0; x < 4; x++) acc[i][j][x] = 0.f;

    loadTile(0, 0); cpcommit();
    loadTile(1, 1); cpcommit();

    for (int t = 0; t < NTT; ++t) {
        if (t + 1 < NTT) cpwait1(); else cpwait0();   // tile t fully landed
        __syncthreads();
        if (t + 2 < NTT) { loadTile(t + 2, (t + 2) % 3); cpcommit(); }

        const uint32_t aB = sb + (t % 3) * ASTG;
        const uint32_t wB = sb + 3 * ASTG + (t % 3) * WSTG;

#pragma unroll
        for (int s = 0; s < 4; ++s) {               // 4 x k16 per tile
            uint32_t af[4][4], bf[4][4];
#pragma unroll
            for (int i = 0; i < 4; i++) {
                if (ACH) {
                    const int krow = s * 16 + (tt >> 1) * 8 + r;
                    const int mch = ((mw + i * 16) >> 3) + (tt & 1);
                    ldsm4t(af[i], aB + krow * 256 + ((mch ^ r) * 16));
                } else {
                    const int row = mw + i * 16 + (tt & 1) * 8 + r;
                    const int kch = s * 2 + (tt >> 1);
                    ldsm4(af[i], aB + row * 128 + ((kch ^ r) * 16));
                }
            }
#pragma unroll
            for (int jp = 0; jp < 4; jp++) {
                const int e = nw + jp * 16 + (tt >> 1) * 8 + r;
                const int kch = s * 2 + (tt & 1);
                ldsm4(bf[jp], wB + e * 128 + ((kch ^ r) * 16));
            }
#pragma unroll
            for (int i = 0; i < 4; i++)
#pragma unroll
                for (int j = 0; j < 8; j++)
                    mma_f16(acc[i][j], af[i], &bf[j >> 1][(j & 1) * 2]);
        }
    }

    // epilogue: channel-major Cout[b*E*S + e*S + s] + bias
    float* Cblk = Cout + (size_t)b * E_ * S_ + (size_t)e0 * S_ + s0;
#pragma unroll
    for (int i = 0; i < 4; i++) {
        const int mr = mw + i * 16 + g;
#pragma unroll
        for (int j = 0; j < 8; j++) {
            const int e = nw + j * 8 + q * 2;
            const float bv0 = __ldg(bias + e0 + e);
            const float bv1 = __ldg(bias + e0 + e + 1);
            Cblk[(size_t)e * S_ + mr] = acc[i][j][0] + bv0;
            Cblk[(size_t)(e + 1) * S_ + mr] = acc[i][j][1] + bv1;
            Cblk[(size_t)e * S_ + mr + 8] = acc[i][j][2] + bv0;
            Cblk[(size_t)(e + 1) * S_ + mr + 8] = acc[i][j][3] + bv1;
        }
    }
}

// ------------------------------- Scan --------------------------------------

__device__ __forceinline__ float sigm(float x) { return 1.0f / (1.0f + __expf(-x)); }
__device__ __forceinline__ void step_cv(float gg, float hh, float& c, float& v) {
    const float z = sigm(gg);
    c = 1.0f - z;
    const float gl = (hh >= 0.f) ? (hh + 0.5f) : sigm(hh);
    v = z * gl;
}

// gh: (B,2H,S) f32. TOKOUT=false -> half (B,H,S) (feeds GEMM1);
// TOKOUT=true -> f32 (B,S,H) via smem transpose.
template <bool TOKOUT>
__global__ __launch_bounds__(256) void scan_kernel(
    const float* __restrict__ gh, void* __restrict__ outv)
{
    __shared__ float stg[2080];
    const int tid = threadIdx.x, w = tid >> 5, lane = tid & 31;
    const int gw = blockIdx.x * 8 + w;
    const int b = gw >> 10;
    const int h = gw & 1023;
    const int h0 = (blockIdx.x * 8) & 1023;

    const float* gate = gh + ((size_t)b * E_ + h) * S_;
    const float* hid = gate + (size_t)H_ * S_;

    float hprev = 0.5f;

    for (int iter = 0; iter < 8; ++iter) {
        const int sbase = iter * 512 + lane * 16;
        const float4* g4 = (const float4*)(gate + sbase);
        const float4* h4 = (const float4*)(hid + sbase);

        float c[16], v[16];
        float C = 1.f, V = 0.f;
#pragma unroll
        for (int i = 0; i < 4; i++) {
            const float4 gv = __ldg(g4 + i);
            const float4 hv = __ldg(h4 + i);
            const float* gp = (const float*)&gv;
            const float* hp = (const float*)&hv;
#pragma unroll
            for (int j = 0; j < 4; j++) {
                step_cv(gp[j], hp[j], c[i * 4 + j], v[i * 4 + j]);
                V = __fmaf_rn(c[i * 4 + j], V, v[i * 4 + j]);
                C *= c[i * 4 + j];
            }
        }

        float Ci = C, Vi = V;
#pragma unroll
        for (int d = 1; d < 32; d <<= 1) {
            const float Cu = __shfl_up_sync(0xffffffffu, Ci, d);
            const float Vu = __shfl_up_sync(0xffffffffu, Vi, d);
            if (lane >= d) { Vi = __fmaf_rn(Ci, Vu, Vi); Ci *= Cu; }
        }
        const float C31 = __shfl_sync(0xffffffffu, Ci, 31);
        const float V31 = __shfl_sync(0xffffffffu, Vi, 31);
        const float Ce = __shfl_up_sync(0xffffffffu, Ci, 1);
        const float Ve = __shfl_up_sync(0xffffffffu, Vi, 1);
        float hcur = (lane == 0) ? hprev : __fmaf_rn(Ce, hprev, Ve);
        hprev = __fmaf_rn(C31, hprev, V31);

        float hv16[16];
#pragma unroll
        for (int i = 0; i < 16; i++) {
            hcur = __fmaf_rn(c[i], hcur, v[i]);
            hv16[i] = hcur;
        }

        if (!TOKOUT) {
            __half* outh = (__half*)outv + (size_t)b * H_ * S_ + (size_t)h * S_ + sbase;
            uint32_t u[8];
#pragma unroll
            for (int i = 0; i < 8; i++) {
                const __half2 h2 = __floats2half2_rn(hv16[2 * i], hv16[2 * i + 1]);
                u[i] = *(const uint32_t*)&h2;
            }
            ((uint4*)outh)[0] = make_uint4(u[0], u[1], u[2], u[3]);
            ((uint4*)outh)[1] = make_uint4(u[4], u[5], u[6], u[7]);
        } else {
            float* out = (float*)outv;
#pragma unroll
            for (int c2 = 0; c2 < 2; ++c2) {
#pragma unroll
                for (int t = 0; t < 8; t++) stg[lane * 65 + t * 8 + w] = hv16[c2 * 8 + t];
                __syncthreads();
#pragma unroll
                for (int i = 0; i < 2; i++) {
                    const int f = i * 256 + tid;
                    const int half_ = f & 1, t = (f >> 1) & 7, l = f >> 4;
                    const int base = l * 65 + t * 8 + half_ * 4;
                    float4 o;
                    o.x = stg[base]; o.y = stg[base + 1];
                    o.z = stg[base + 2]; o.w = stg[base + 3];
                    const int s = iter * 512 + l * 16 + c2 * 8 + t;
                    *(float4*)(out + ((size_t)b * S_ + s) * H_ + h0 + half_ * 4) = o;
                }
                __syncthreads();
            }
        }
    }
}

// ------------------------------ Launch -------------------------------------

extern "C" void kernel_launch(void* const* d_in, const int* in_sizes, int n_in,
                              void* d_out, int out_size)
{
    (void)in_sizes; (void)n_in; (void)out_size;
    const float* x = (const float*)d_in[0];
    const float* W0 = (const float*)d_in[1];
    const float* b0 = (const float*)d_in[2];
    const float* W1 = (const float*)d_in[3];
    const float* b1 = (const float*)d_in[4];
    float* out = (float*)d_out;

    float* gbuf;
    __half *h1h, *xh, *w0h, *w1h;
    cudaGetSymbolAddress((void**)&gbuf, g_gbuf);
    cudaGetSymbolAddress((void**)&h1h, g_h1h);
    cudaGetSymbolAddress((void**)&xh, g_xh);
    cudaGetSymbolAddress((void**)&w0h, g_w0h);
    cudaGetSymbolAddress((void**)&w1h, g_w1h);

    cudaFuncSetAttribute(gemm_kernel<false>,
                         cudaFuncAttributeMaxDynamicSharedMemorySize, SMEM_GEMM);
    cudaFuncSetAttribute(gemm_kernel<true>,
                         cudaFuncAttributeMaxDynamicSharedMemorySize, SMEM_GEMM);

    tohalf_kernel<<<(int)((size_t)M_ * K_ / 1024), 256>>>(x, xh);
    tohalf_kernel<<<(int)((size_t)E_ * K_ / 1024), 256>>>(W0, w0h);
    tohalf_kernel<<<(int)((size_t)E_ * K_ / 1024), 256>>>(W1, w1h);

    const dim3 gGrid(E_ / BN, M_ / BM);     // (16, 256)
    const int scanBlocks = (B_ * H_) / 8;   // 1024

    gemm_kernel<false><<<gGrid, 128, SMEM_GEMM>>>(xh, w0h, b0, gbuf);
    scan_kernel<false><<<scanBlocks, 256>>>(gbuf, h1h);
    gemm_kernel<true><<<gGrid, 128, SMEM_GEMM>>>(h1h, w1h, b1, gbuf);
    scan_kernel<true><<<scanBlocks, 256>>>(gbuf, out);
}